// round 2
// baseline (speedup 1.0000x reference)
#include <cuda_runtime.h>

// Resampling: 3D affine grid-sample, trilinear, fp32.
// Shapes: fmap (B=16, P=8, H=32, W=32, D=32, C=8), theta (B, 12*P).
// One thread per output voxel (b,p,h,w,d); computes all C=8 channels.
// Each 256-thread block lies entirely within one (b,p) slice -> theta is
// block-uniform; stage it through shared memory.

#define RS_B 16
#define RS_P 8
#define RS_H 32
#define RS_W 32
#define RS_D 32
#define RS_C 8
#define RS_VOX (RS_H * RS_W * RS_D)   // 32768 voxels per (b,p) slice

__global__ __launch_bounds__(256) void resample_kernel(
    const float* __restrict__ fmap,
    const float* __restrict__ theta,
    float* __restrict__ out)
{
    __shared__ float t[12];

    const int gid   = blockIdx.x * 256 + threadIdx.x;   // 0 .. B*P*VOX-1
    const int slice = gid >> 15;                        // b*P + p  (VOX = 2^15)
    const int n     = gid & (RS_VOX - 1);               // voxel within slice

    // theta row: b*96 + p*12 floats (B,P,3,4) — block-uniform
    if (threadIdx.x < 12) {
        const int bslice = (blockIdx.x * 256) >> 15;
        t[threadIdx.x] = theta[(bslice >> 3) * (12 * RS_P)
                               + (bslice & (RS_P - 1)) * 12 + threadIdx.x];
    }
    __syncthreads();

    // n = (h*W + w)*D + d ; grid point is (xs[w], ys[h], zs[d])
    const int h = n >> 10;
    const int w = (n >> 5) & 31;
    const int d = n & 31;

    const float step = 2.0f / 31.0f;
    const float gx = fmaf((float)w, step, -1.0f);
    const float gy = fmaf((float)h, step, -1.0f);
    const float gz = fmaf((float)d, step, -1.0f);

    // [x';y';z'] = th(3x4) @ [gx,gy,gz,1]
    const float xp = t[0] * gx + t[1] * gy + t[2]  * gz + t[3];
    const float yp = t[4] * gx + t[5] * gy + t[6]  * gz + t[7];
    const float zp = t[8] * gx + t[9] * gy + t[10] * gz + t[11];

    // map to voxel coords with (dim-2) scaling, exactly as reference
    const float x = 0.5f * (xp + 1.0f) * (float)(RS_W - 2);
    const float y = 0.5f * (yp + 1.0f) * (float)(RS_H - 2);
    const float z = 0.5f * (zp + 1.0f) * (float)(RS_D - 2);

    int x0 = (int)floorf(x); int x1 = x0 + 1;
    int y0 = (int)floorf(y); int y1 = y0 + 1;
    int z0 = (int)floorf(z); int z1 = z0 + 1;
    x0 = min(max(x0, 0), RS_W - 1); x1 = min(max(x1, 0), RS_W - 1);
    y0 = min(max(y0, 0), RS_H - 1); y1 = min(max(y1, 0), RS_H - 1);
    z0 = min(max(z0, 0), RS_D - 1); z1 = min(max(z1, 0), RS_D - 1);

    // weights computed from CLAMPED corners (reference semantics)
    const float xd = x - (float)x0;        // weight for x1; (1-xd) for x0
    const float yd = (float)y1 - y;        // weight for y0; (1-yd) for y1
    const float zd = z - (float)z0;        // weight for z1; (1-zd) for z0

    const float wx0 = 1.0f - xd, wx1 = xd;
    const float wy0 = yd,        wy1 = 1.0f - yd;
    const float wz0 = 1.0f - zd, wz1 = zd;

    const float* base = fmap + (size_t)slice * (RS_VOX * RS_C);

    float4 acc0 = make_float4(0.f, 0.f, 0.f, 0.f);
    float4 acc1 = make_float4(0.f, 0.f, 0.f, 0.f);

    const int iy[2] = { y0, y1 };
    const int ix[2] = { x0, x1 };
    const int iz[2] = { z0, z1 };
    const float wy[2] = { wy0, wy1 };
    const float wx[2] = { wx0, wx1 };
    const float wz[2] = { wz0, wz1 };

#pragma unroll
    for (int a = 0; a < 2; ++a) {
#pragma unroll
        for (int b2 = 0; b2 < 2; ++b2) {
            const int rowbase = (iy[a] * RS_W + ix[b2]) * RS_D;
            const float wxy = wy[a] * wx[b2];
#pragma unroll
            for (int c2 = 0; c2 < 2; ++c2) {
                const float wgt = wxy * wz[c2];
                const float4* p = (const float4*)(base + (size_t)(rowbase + iz[c2]) * RS_C);
                const float4 v0 = __ldg(p);
                const float4 v1 = __ldg(p + 1);
                acc0.x = fmaf(wgt, v0.x, acc0.x);
                acc0.y = fmaf(wgt, v0.y, acc0.y);
                acc0.z = fmaf(wgt, v0.z, acc0.z);
                acc0.w = fmaf(wgt, v0.w, acc0.w);
                acc1.x = fmaf(wgt, v1.x, acc1.x);
                acc1.y = fmaf(wgt, v1.y, acc1.y);
                acc1.z = fmaf(wgt, v1.z, acc1.z);
                acc1.w = fmaf(wgt, v1.w, acc1.w);
            }
        }
    }

    float4* op = (float4*)(out + (size_t)gid * RS_C);
    op[0] = acc0;
    op[1] = acc1;
}

extern "C" void kernel_launch(void* const* d_in, const int* in_sizes, int n_in,
                              void* d_out, int out_size)
{
    const float* fmap  = (const float*)d_in[0];
    const float* theta = (const float*)d_in[1];
    float* out = (float*)d_out;

    const int total = RS_B * RS_P * RS_VOX;   // 4,194,304 threads
    resample_kernel<<<total / 256, 256>>>(fmap, theta, out);
}